// round 6
// baseline (speedup 1.0000x reference)
#include <cuda_runtime.h>

// Ende_3332894622093: B=65536, D=40, HB=20.
// out = [t1 | s2] (B,1,40);  J_T (B,40,40) =
//   [[diag(e4)+JJ12@J21, JJ12*e2], [J21, diag(e2)]]
// d_out: out flattened (n*40) then J_T flattened (n*1600).
//
// Mapping: thread -> (item = tid/20, j = tid%20). Phase D/E use paired
// columns: lanes (je, je+1) both hold J21[:, je..je+1] (float2); the even
// lane produces rows 0..9 of TL/TR, the odd lane rows 10..19.
// R6: __launch_bounds__(320,3) for occupancy; phase-E accumulates directly
// from float4 (no jrow unpack) to fit the register budget.

#define IPB 16            // items per block (65536 % 16 == 0)
#define TPB (IPB * 20)    // 320 threads
#define WSS 560           // per-item smem stride (floats); 560 mod 32 = 16 banks
// per-item: xs[0..40) bb[40..80) s2s[80..100) jjs[100..500) e2s[500..520) e4s[520..540)

__global__ __launch_bounds__(TPB, 3)
void ende_kernel(const float* __restrict__ src,
                 const float* __restrict__ w1,
                 const float* __restrict__ w2,
                 const float* __restrict__ w3,
                 const float* __restrict__ w4,
                 float* __restrict__ outp,
                 float* __restrict__ jt,
                 int n)
{
    __shared__ float w1s[400], w2s[400], w3s[400], w4s[400];
    __shared__ __align__(16) float ws[IPB * WSS];

    const int tid = threadIdx.x;
    for (int i = tid; i < 400; i += TPB) {
        w1s[i] = w1[i];
        w2s[i] = w2[i];
        w3s[i] = w3[i];
        w4s[i] = w4[i];
    }

    const int itemL = tid / 20;
    const int j     = tid % 20;
    const int b     = blockIdx.x * IPB + itemL;
    const bool act  = (b < n);
    float* S = &ws[itemL * WSS];

    // ---- cooperative x load ----
    if (tid < IPB * 10) {
        int it = tid / 10, c = tid % 10;
        if (blockIdx.x * IPB + it < n) {
            float4 v = ((const float4*)(src + (size_t)(blockIdx.x * IPB + it) * 40))[c];
            *(float4*)&ws[it * WSS + c * 4] = v;
        }
    }
    __syncthreads();

    // ---- phase B: f1, f2, e2, (b1,b2), s2 ----
    float s2j;
    {
        float acc1 = 0.f, acc2 = 0.f;
        const float4* xv  = (const float4*)S;
        const float4* w1r = (const float4*)&w1s[j * 20];
        const float4* w2r = (const float4*)&w2s[j * 20];
        #pragma unroll
        for (int k4 = 0; k4 < 5; k4++) {
            float4 xx = xv[k4], a = w1r[k4], c = w2r[k4];
            acc1 += xx.x * a.x + xx.y * a.y + xx.z * a.z + xx.w * a.w;
            acc2 += xx.x * c.x + xx.y * c.y + xx.z * c.z + xx.w * c.w;
        }
        float f1 = tanhf(acc1);
        float f2 = tanhf(acc2);
        float e2 = expf(f2);
        float p2  = S[20 + j];
        float p2e = p2 * e2;
        s2j = p2e + f1;
        ((float2*)&S[40])[j] = make_float2(1.f - f1 * f1, p2e * (1.f - f2 * f2));
        S[80 + j]  = s2j;
        S[500 + j] = e2;
    }
    __syncthreads();

    // ---- phase C: f3, f4, e4, t1, JJ12 row j ----
    {
        float acc3 = 0.f, acc4 = 0.f;
        const float4* sv  = (const float4*)&S[80];
        const float4* w3r = (const float4*)&w3s[j * 20];
        const float4* w4r = (const float4*)&w4s[j * 20];
        #pragma unroll
        for (int k4 = 0; k4 < 5; k4++) {
            float4 xx = sv[k4], a = w3r[k4], c = w4r[k4];
            acc3 += xx.x * a.x + xx.y * a.y + xx.z * a.z + xx.w * a.w;
            acc4 += xx.x * c.x + xx.y * c.y + xx.z * c.z + xx.w * c.w;
        }
        float f3 = tanhf(acc3);
        float f4 = tanhf(acc4);
        float e4 = expf(f4);
        float s1  = S[j];
        float s1e = s1 * e4;
        float a3 = 1.f - f3 * f3;
        float a4 = s1e * (1.f - f4 * f4);
        float4* jj = (float4*)&S[100 + j * 20];
        #pragma unroll
        for (int k4 = 0; k4 < 5; k4++) {
            float4 a_ = *(const float4*)&w3s[j * 20 + 4 * k4];
            float4 c_ = *(const float4*)&w4s[j * 20 + 4 * k4];
            float4 r;
            r.x = a3 * a_.x + a4 * c_.x;
            r.y = a3 * a_.y + a4 * c_.y;
            r.z = a3 * a_.z + a4 * c_.z;
            r.w = a3 * a_.w + a4 * c_.w;
            jj[k4] = r;
        }
        S[520 + j] = e4;
        if (act) {
            outp[(size_t)b * 40 + j]      = s1e + f3;  // t1
            outp[(size_t)b * 40 + 20 + j] = s2j;
        }
    }
    __syncthreads();

    float* J = jt + (size_t)b * 1600;
    const int p  = j & 1;
    const int je = j & ~1;

    // ---- phase D: my_col2 = J21[:, je..je+1] (both lanes of pair, dup) ----
    float2 mc[20];
    #pragma unroll
    for (int kk = 0; kk < 10; kk++) {
        float4 bbp = *(const float4*)&S[40 + 4 * kk];  // (b1,b2) for k=2kk,2kk+1
        #pragma unroll
        for (int s = 0; s < 2; s++) {
            int k = 2 * kk + s;
            float b1v = s ? bbp.z : bbp.x;
            float b2v = s ? bbp.w : bbp.y;
            float2 wa = *(const float2*)&w1s[k * 20 + je];
            float2 wb = *(const float2*)&w2s[k * 20 + je];
            mc[k].x = b1v * wa.x + b2v * wb.x;
            mc[k].y = b1v * wa.y + b2v * wb.y;
        }
    }

    const float2 e2p = *(const float2*)&S[500 + je];
    const float2 e4p = *(const float2*)&S[520 + je];

    // ---- BL/BR stores: even lane rows k=0..9, odd lane k=10..19 ----
    if (act) {
        const int kbase = p ? 10 : 0;
        #pragma unroll
        for (int kk = 0; kk < 10; kk++) {
            int k = kbase + kk;
            __stcs((float2*)&J[(20 + k) * 40 + je], mc[k]);
            float2 br = make_float2(k == je ? e2p.x : 0.f,
                                    k == je + 1 ? e2p.y : 0.f);
            __stcs((float2*)&J[(20 + k) * 40 + 20 + je], br);
        }
    }

    // ---- phase E: even lane rows i=0..9, odd rows 10..19; cols je,je+1 ----
    const int ibase = p ? 10 : 0;
    #pragma unroll
    for (int ii = 0; ii < 10; ii++) {
        int i = ibase + ii;
        const float4* jjr = (const float4*)&S[100 + i * 20];
        float2 acc = make_float2(0.f, 0.f);
        #pragma unroll
        for (int k4 = 0; k4 < 5; k4++) {
            float4 v = jjr[k4];
            acc.x += v.x * mc[4*k4+0].x + v.y * mc[4*k4+1].x
                   + v.z * mc[4*k4+2].x + v.w * mc[4*k4+3].x;
            acc.y += v.x * mc[4*k4+0].y + v.y * mc[4*k4+1].y
                   + v.z * mc[4*k4+2].y + v.w * mc[4*k4+3].y;
        }
        if (i == je)     acc.x += e4p.x;
        if (i == je + 1) acc.y += e4p.y;
        float2 jp = *(const float2*)&S[100 + i * 20 + je];
        float2 tr = make_float2(jp.x * e2p.x, jp.y * e2p.y);
        if (act) {
            __stcs((float2*)&J[i * 40 + je], acc);
            __stcs((float2*)&J[i * 40 + 20 + je], tr);
        }
    }
}

extern "C" void kernel_launch(void* const* d_in, const int* in_sizes, int n_in,
                              void* d_out, int out_size)
{
    const float* src = (const float*)d_in[0];
    const float* w1  = (const float*)d_in[1];
    const float* w2  = (const float*)d_in[2];
    const float* w3  = (const float*)d_in[3];
    const float* w4  = (const float*)d_in[4];

    int n = in_sizes[0] / 40;
    float* outp = (float*)d_out;
    float* jt   = (float*)d_out + (size_t)n * 40;

    int blocks = (n + IPB - 1) / IPB;
    ende_kernel<<<blocks, TPB>>>(src, w1, w2, w3, w4, outp, jt, n);
}

// round 7
// speedup vs baseline: 1.1091x; 1.1091x over previous
#include <cuda_runtime.h>

// Ende_3332894622093: B=65536, D=40, HB=20.
// out = [t1 | s2] (B,1,40);  J_T (B,40,40) =
//   [[diag(e4)+JJ12@J21, JJ12*e2], [J21, diag(e2)]]
// d_out: out flattened (n*40) then J_T flattened (n*1600).
//
// Mapping: thread -> (item = tid/20, j = tid%20). Phase D/E use paired
// columns: lanes (je, je+1) both hold J21[:, je..je+1] (float2); the even
// lane produces rows 0..9 of TL/TR, the odd lane rows 10..19.
// R7: 160-thread blocks, __launch_bounds__(160,5) -> 81-reg cap, 25 warps/SM.

#define IPB 8             // items per block (65536 % 8 == 0)
#define TPB (IPB * 20)    // 160 threads
#define WSS 560           // per-item smem stride (floats); 560 mod 32 = 16 banks
// per-item: xs[0..40) bb[40..80) s2s[80..100) jjs[100..500) e2s[500..520) e4s[520..540)

__global__ __launch_bounds__(TPB, 5)
void ende_kernel(const float* __restrict__ src,
                 const float* __restrict__ w1,
                 const float* __restrict__ w2,
                 const float* __restrict__ w3,
                 const float* __restrict__ w4,
                 float* __restrict__ outp,
                 float* __restrict__ jt,
                 int n)
{
    __shared__ float w1s[400], w2s[400], w3s[400], w4s[400];
    __shared__ __align__(16) float ws[IPB * WSS];

    const int tid = threadIdx.x;
    for (int i = tid; i < 400; i += TPB) {
        w1s[i] = w1[i];
        w2s[i] = w2[i];
        w3s[i] = w3[i];
        w4s[i] = w4[i];
    }

    const int itemL = tid / 20;
    const int j     = tid % 20;
    const int b     = blockIdx.x * IPB + itemL;
    const bool act  = (b < n);
    float* S = &ws[itemL * WSS];

    // ---- cooperative x load ----
    if (tid < IPB * 10) {
        int it = tid / 10, c = tid % 10;
        if (blockIdx.x * IPB + it < n) {
            float4 v = ((const float4*)(src + (size_t)(blockIdx.x * IPB + it) * 40))[c];
            *(float4*)&ws[it * WSS + c * 4] = v;
        }
    }
    __syncthreads();

    // ---- phase B: f1, f2, e2, (b1,b2), s2 ----
    float s2j;
    {
        float acc1 = 0.f, acc2 = 0.f;
        const float4* xv  = (const float4*)S;
        const float4* w1r = (const float4*)&w1s[j * 20];
        const float4* w2r = (const float4*)&w2s[j * 20];
        #pragma unroll
        for (int k4 = 0; k4 < 5; k4++) {
            float4 xx = xv[k4], a = w1r[k4], c = w2r[k4];
            acc1 += xx.x * a.x + xx.y * a.y + xx.z * a.z + xx.w * a.w;
            acc2 += xx.x * c.x + xx.y * c.y + xx.z * c.z + xx.w * c.w;
        }
        float f1 = tanhf(acc1);
        float f2 = tanhf(acc2);
        float e2 = expf(f2);
        float p2  = S[20 + j];
        float p2e = p2 * e2;
        s2j = p2e + f1;
        ((float2*)&S[40])[j] = make_float2(1.f - f1 * f1, p2e * (1.f - f2 * f2));
        S[80 + j]  = s2j;
        S[500 + j] = e2;
    }
    __syncthreads();

    // ---- phase C: f3, f4, e4, t1, JJ12 row j ----
    {
        float acc3 = 0.f, acc4 = 0.f;
        const float4* sv  = (const float4*)&S[80];
        const float4* w3r = (const float4*)&w3s[j * 20];
        const float4* w4r = (const float4*)&w4s[j * 20];
        #pragma unroll
        for (int k4 = 0; k4 < 5; k4++) {
            float4 xx = sv[k4], a = w3r[k4], c = w4r[k4];
            acc3 += xx.x * a.x + xx.y * a.y + xx.z * a.z + xx.w * a.w;
            acc4 += xx.x * c.x + xx.y * c.y + xx.z * c.z + xx.w * c.w;
        }
        float f3 = tanhf(acc3);
        float f4 = tanhf(acc4);
        float e4 = expf(f4);
        float s1  = S[j];
        float s1e = s1 * e4;
        float a3 = 1.f - f3 * f3;
        float a4 = s1e * (1.f - f4 * f4);
        float4* jj = (float4*)&S[100 + j * 20];
        #pragma unroll
        for (int k4 = 0; k4 < 5; k4++) {
            float4 a_ = *(const float4*)&w3s[j * 20 + 4 * k4];
            float4 c_ = *(const float4*)&w4s[j * 20 + 4 * k4];
            float4 r;
            r.x = a3 * a_.x + a4 * c_.x;
            r.y = a3 * a_.y + a4 * c_.y;
            r.z = a3 * a_.z + a4 * c_.z;
            r.w = a3 * a_.w + a4 * c_.w;
            jj[k4] = r;
        }
        S[520 + j] = e4;
        if (act) {
            outp[(size_t)b * 40 + j]      = s1e + f3;  // t1
            outp[(size_t)b * 40 + 20 + j] = s2j;
        }
    }
    __syncthreads();

    float* J = jt + (size_t)b * 1600;
    const int p  = j & 1;
    const int je = j & ~1;

    // ---- phase D: my_col2 = J21[:, je..je+1] (both lanes of pair, dup) ----
    float2 mc[20];
    #pragma unroll
    for (int kk = 0; kk < 10; kk++) {
        float4 bbp = *(const float4*)&S[40 + 4 * kk];  // (b1,b2) for k=2kk,2kk+1
        #pragma unroll
        for (int s = 0; s < 2; s++) {
            int k = 2 * kk + s;
            float b1v = s ? bbp.z : bbp.x;
            float b2v = s ? bbp.w : bbp.y;
            float2 wa = *(const float2*)&w1s[k * 20 + je];
            float2 wb = *(const float2*)&w2s[k * 20 + je];
            mc[k].x = b1v * wa.x + b2v * wb.x;
            mc[k].y = b1v * wa.y + b2v * wb.y;
        }
    }

    const float2 e2p = *(const float2*)&S[500 + je];
    const float2 e4p = *(const float2*)&S[520 + je];

    // ---- BL/BR stores: even lane rows k=0..9, odd lane k=10..19 ----
    if (act) {
        const int kbase = p ? 10 : 0;
        #pragma unroll
        for (int kk = 0; kk < 10; kk++) {
            int k = kbase + kk;
            __stcs((float2*)&J[(20 + k) * 40 + je], mc[k]);
            float2 br = make_float2(k == je ? e2p.x : 0.f,
                                    k == je + 1 ? e2p.y : 0.f);
            __stcs((float2*)&J[(20 + k) * 40 + 20 + je], br);
        }
    }

    // ---- phase E: even lane rows i=0..9, odd rows 10..19; cols je,je+1 ----
    const int ibase = p ? 10 : 0;
    #pragma unroll
    for (int ii = 0; ii < 10; ii++) {
        int i = ibase + ii;
        const float4* jjr = (const float4*)&S[100 + i * 20];
        float2 acc = make_float2(0.f, 0.f);
        #pragma unroll
        for (int k4 = 0; k4 < 5; k4++) {
            float4 v = jjr[k4];
            acc.x += v.x * mc[4*k4+0].x + v.y * mc[4*k4+1].x
                   + v.z * mc[4*k4+2].x + v.w * mc[4*k4+3].x;
            acc.y += v.x * mc[4*k4+0].y + v.y * mc[4*k4+1].y
                   + v.z * mc[4*k4+2].y + v.w * mc[4*k4+3].y;
        }
        if (i == je)     acc.x += e4p.x;
        if (i == je + 1) acc.y += e4p.y;
        float2 jp = *(const float2*)&S[100 + i * 20 + je];
        float2 tr = make_float2(jp.x * e2p.x, jp.y * e2p.y);
        if (act) {
            __stcs((float2*)&J[i * 40 + je], acc);
            __stcs((float2*)&J[i * 40 + 20 + je], tr);
        }
    }
}

extern "C" void kernel_launch(void* const* d_in, const int* in_sizes, int n_in,
                              void* d_out, int out_size)
{
    const float* src = (const float*)d_in[0];
    const float* w1  = (const float*)d_in[1];
    const float* w2  = (const float*)d_in[2];
    const float* w3  = (const float*)d_in[3];
    const float* w4  = (const float*)d_in[4];

    int n = in_sizes[0] / 40;
    float* outp = (float*)d_out;
    float* jt   = (float*)d_out + (size_t)n * 40;

    int blocks = (n + IPB - 1) / IPB;
    ende_kernel<<<blocks, TPB>>>(src, w1, w2, w3, w4, outp, jt, n);
}

// round 8
// speedup vs baseline: 1.3515x; 1.2186x over previous
#include <cuda_runtime.h>

// Ende_3332894622093: B=65536, D=40, HB=20.
// out = [t1 | s2] (B,1,40);  J_T (B,40,40) =
//   [[diag(e4)+JJ12@J21, JJ12*e2], [J21, diag(e2)]]
// d_out: out flattened (n*40) then J_T flattened (n*1600).
//
// R8: k-outer phase D/E fusion. Lane pair (je,je+1): each lane keeps 10 TL row
// accumulators (float2, 20 regs) instead of the full J21 column pair (40 regs).
// JJ12 is staged TRANSPOSED (jjt[k][i], row stride 24, pad at i=10) so each
// lane reads a uniform aligned f4+f4+f2 10-float segment per k.

#define IPB 8             // items per block
#define TPB (IPB * 20)    // 160 threads
#define WSS 624           // per-item smem stride (floats); 624 mod 32 = 16
// per-item: xs[0..40) bb[40..80) s2[80..100) e2[100..120) e4[120..140) jjt[144..624)
#define XS  0
#define BB  40
#define S2  80
#define E2  100
#define E4  120
#define JJT 144
#define JST 24            // jjt row stride

__global__ __launch_bounds__(TPB, 5)
void ende_kernel(const float* __restrict__ src,
                 const float* __restrict__ w1,
                 const float* __restrict__ w2,
                 const float* __restrict__ w3,
                 const float* __restrict__ w4,
                 float* __restrict__ outp,
                 float* __restrict__ jt,
                 int n)
{
    __shared__ float w1s[400], w2s[400], w3s[400], w4s[400];
    __shared__ __align__(16) float ws[IPB * WSS];

    const int tid = threadIdx.x;
    for (int i = tid; i < 400; i += TPB) {
        w1s[i] = w1[i];
        w2s[i] = w2[i];
        w3s[i] = w3[i];
        w4s[i] = w4[i];
    }

    const int itemL = tid / 20;
    const int j     = tid % 20;
    const int b     = blockIdx.x * IPB + itemL;
    const bool act  = (b < n);
    float* S = &ws[itemL * WSS];

    // ---- cooperative x load ----
    if (tid < IPB * 10) {
        int it = tid / 10, c = tid % 10;
        if (blockIdx.x * IPB + it < n) {
            float4 v = ((const float4*)(src + (size_t)(blockIdx.x * IPB + it) * 40))[c];
            *(float4*)&ws[it * WSS + c * 4] = v;
        }
    }
    __syncthreads();

    // ---- phase B: f1, f2, e2, (b1,b2), s2 ----
    float s2j;
    {
        float acc1 = 0.f, acc2 = 0.f;
        const float4* xv  = (const float4*)&S[XS];
        const float4* w1r = (const float4*)&w1s[j * 20];
        const float4* w2r = (const float4*)&w2s[j * 20];
        #pragma unroll
        for (int k4 = 0; k4 < 5; k4++) {
            float4 xx = xv[k4], a = w1r[k4], c = w2r[k4];
            acc1 += xx.x * a.x + xx.y * a.y + xx.z * a.z + xx.w * a.w;
            acc2 += xx.x * c.x + xx.y * c.y + xx.z * c.z + xx.w * c.w;
        }
        float f1 = tanhf(acc1);
        float f2 = tanhf(acc2);
        float e2 = expf(f2);
        float p2  = S[XS + 20 + j];
        float p2e = p2 * e2;
        s2j = p2e + f1;
        ((float2*)&S[BB])[j] = make_float2(1.f - f1 * f1, p2e * (1.f - f2 * f2));
        S[S2 + j] = s2j;
        S[E2 + j] = e2;
    }
    __syncthreads();

    // ---- phase C: f3, f4, e4, t1, JJ12 row j -> jjt column (transposed) ----
    {
        float acc3 = 0.f, acc4 = 0.f;
        const float4* sv  = (const float4*)&S[S2];
        const float4* w3r = (const float4*)&w3s[j * 20];
        const float4* w4r = (const float4*)&w4s[j * 20];
        #pragma unroll
        for (int k4 = 0; k4 < 5; k4++) {
            float4 xx = sv[k4], a = w3r[k4], c = w4r[k4];
            acc3 += xx.x * a.x + xx.y * a.y + xx.z * a.z + xx.w * a.w;
            acc4 += xx.x * c.x + xx.y * c.y + xx.z * c.z + xx.w * c.w;
        }
        float f3 = tanhf(acc3);
        float f4 = tanhf(acc4);
        float e4 = expf(f4);
        float s1  = S[XS + j];
        float s1e = s1 * e4;
        float a3 = 1.f - f3 * f3;
        float a4 = s1e * (1.f - f4 * f4);
        const int scol = j + (j >= 10 ? 2 : 0);   // pad slot at i=10,11
        #pragma unroll
        for (int k4 = 0; k4 < 5; k4++) {
            float4 a_ = w3r[k4], c_ = w4r[k4];
            S[JJT + (4 * k4 + 0) * JST + scol] = a3 * a_.x + a4 * c_.x;
            S[JJT + (4 * k4 + 1) * JST + scol] = a3 * a_.y + a4 * c_.y;
            S[JJT + (4 * k4 + 2) * JST + scol] = a3 * a_.z + a4 * c_.z;
            S[JJT + (4 * k4 + 3) * JST + scol] = a3 * a_.w + a4 * c_.w;
        }
        S[E4 + j] = e4;
        if (act) {
            outp[(size_t)b * 40 + j]      = s1e + f3;  // t1
            outp[(size_t)b * 40 + 20 + j] = s2j;
        }
    }
    __syncthreads();

    float* J = jt + (size_t)b * 1600;
    const int p    = j & 1;
    const int je   = j & ~1;
    const int ib12 = p * 12;   // jjt segment offset (pad-adjusted)

    const float2 e2p = *(const float2*)&S[E2 + je];
    const float2 e4p = *(const float2*)&S[E4 + je];

    // ---- fused D/E mainloop over k ----
    float2 acc[10];
    #pragma unroll
    for (int ii = 0; ii < 10; ii++) acc[ii] = make_float2(0.f, 0.f);

    #pragma unroll
    for (int kk = 0; kk < 10; kk++) {
        float4 bbp = *(const float4*)&S[BB + 4 * kk];  // (b1,b2) for k=2kk,2kk+1
        #pragma unroll
        for (int s = 0; s < 2; s++) {
            const int k = 2 * kk + s;
            float b1v = s ? bbp.z : bbp.x;
            float b2v = s ? bbp.w : bbp.y;
            float2 wa = *(const float2*)&w1s[k * 20 + je];
            float2 wb = *(const float2*)&w2s[k * 20 + je];
            float2 mck = make_float2(b1v * wa.x + b2v * wb.x,
                                     b1v * wa.y + b2v * wb.y);
            // BL row k + BR row k, stored by the parity that owns this k range
            if (act && (p == (k >= 10 ? 1 : 0))) {
                __stcs((float2*)&J[(20 + k) * 40 + je], mck);
                float2 br = make_float2(k == je ? e2p.x : 0.f,
                                        k == je + 1 ? e2p.y : 0.f);
                __stcs((float2*)&J[(20 + k) * 40 + 20 + je], br);
            }
            // accumulate TL rows: jjt[k][ibase..ibase+9]
            const float* jr = &S[JJT + k * JST + ib12];
            float4 ja = *(const float4*)jr;
            float4 jb = *(const float4*)(jr + 4);
            float2 jc = *(const float2*)(jr + 8);
            acc[0].x += ja.x * mck.x; acc[0].y += ja.x * mck.y;
            acc[1].x += ja.y * mck.x; acc[1].y += ja.y * mck.y;
            acc[2].x += ja.z * mck.x; acc[2].y += ja.z * mck.y;
            acc[3].x += ja.w * mck.x; acc[3].y += ja.w * mck.y;
            acc[4].x += jb.x * mck.x; acc[4].y += jb.x * mck.y;
            acc[5].x += jb.y * mck.x; acc[5].y += jb.y * mck.y;
            acc[6].x += jb.z * mck.x; acc[6].y += jb.z * mck.y;
            acc[7].x += jb.w * mck.x; acc[7].y += jb.w * mck.y;
            acc[8].x += jc.x * mck.x; acc[8].y += jc.x * mck.y;
            acc[9].x += jc.y * mck.x; acc[9].y += jc.y * mck.y;
        }
    }

    // ---- TL epilogue: rows ibase..ibase+9, cols je,je+1 ----
    const int ibase = p * 10;
    if (act) {
        #pragma unroll
        for (int ii = 0; ii < 10; ii++) {
            int i = ibase + ii;
            float2 v = acc[ii];
            if (i == je)     v.x += e4p.x;
            if (i == je + 1) v.y += e4p.y;
            __stcs((float2*)&J[i * 40 + je], v);
        }
    }

    // ---- TR epilogue: TR[i][je..je+1] = JJ12[i][je..je+1]*e2 = jjt[je..][i]*e2 ----
    {
        const float* ra = &S[JJT + je * JST + ib12];
        const float* rb = &S[JJT + (je + 1) * JST + ib12];
        float4 a0 = *(const float4*)ra;
        float4 a1 = *(const float4*)(ra + 4);
        float2 a2 = *(const float2*)(ra + 8);
        float4 b0 = *(const float4*)rb;
        float4 b1 = *(const float4*)(rb + 4);
        float2 b2 = *(const float2*)(rb + 8);
        float va[10] = {a0.x,a0.y,a0.z,a0.w,a1.x,a1.y,a1.z,a1.w,a2.x,a2.y};
        float vb[10] = {b0.x,b0.y,b0.z,b0.w,b1.x,b1.y,b1.z,b1.w,b2.x,b2.y};
        if (act) {
            #pragma unroll
            for (int ii = 0; ii < 10; ii++) {
                int i = ibase + ii;
                __stcs((float2*)&J[i * 40 + 20 + je],
                       make_float2(va[ii] * e2p.x, vb[ii] * e2p.y));
            }
        }
    }
}

extern "C" void kernel_launch(void* const* d_in, const int* in_sizes, int n_in,
                              void* d_out, int out_size)
{
    const float* src = (const float*)d_in[0];
    const float* w1  = (const float*)d_in[1];
    const float* w2  = (const float*)d_in[2];
    const float* w3  = (const float*)d_in[3];
    const float* w4  = (const float*)d_in[4];

    int n = in_sizes[0] / 40;
    float* outp = (float*)d_out;
    float* jt   = (float*)d_out + (size_t)n * 40;

    int blocks = (n + IPB - 1) / IPB;
    ende_kernel<<<blocks, TPB>>>(src, w1, w2, w3, w4, outp, jt, n);
}